// round 6
// baseline (speedup 1.0000x reference)
#include <cuda_runtime.h>
#include <cuda_bf16.h>
#include <cstdint>

#define D_MODEL 1024
#define NHEADS  16
#define HDIM    64
#define WINDOW  256
#define BATCH   2
#define SEQ     2048
#define MTOT    (BATCH * SEQ)          /* 4096 */
#define QKV_LD  (3 * D_MODEL)          /* 3072 */

// ---- scratch (no cudaMalloc allowed) --------------------------------------
__device__ float        g_qkv[(size_t)MTOT * QKV_LD];
__device__ __nv_bfloat16 g_xhi[(size_t)MTOT * D_MODEL];
__device__ __nv_bfloat16 g_xlo[(size_t)MTOT * D_MODEL];
__device__ __nv_bfloat16 g_wqh[(size_t)QKV_LD * D_MODEL];
__device__ __nv_bfloat16 g_wql[(size_t)QKV_LD * D_MODEL];
__device__ __nv_bfloat16 g_wph[(size_t)D_MODEL * D_MODEL];
__device__ __nv_bfloat16 g_wpl[(size_t)D_MODEL * D_MODEL];
__device__ __nv_bfloat16 g_ahi[(size_t)MTOT * D_MODEL];
__device__ __nv_bfloat16 g_alo[(size_t)MTOT * D_MODEL];

// ---- PTX helpers (compute_103 baseline: mma.sync + cp.async + ldmatrix) ----
__device__ __forceinline__ uint32_t smem_u32(const void* p) {
    uint32_t a;
    asm("{ .reg .u64 t; cvta.to.shared.u64 t, %1; cvt.u32.u64 %0, t; }" : "=r"(a) : "l"(p));
    return a;
}
__device__ __forceinline__ void cp16(uint32_t dst, const void* src) {
    asm volatile("cp.async.cg.shared.global [%0], [%1], 16;" :: "r"(dst), "l"(src));
}
#define CP_COMMIT()  asm volatile("cp.async.commit_group;" ::: "memory")
#define CP_WAIT(n)   asm volatile("cp.async.wait_group %0;" :: "n"(n) : "memory")

__device__ __forceinline__ void mma_bf16(float* d, uint32_t a0, uint32_t a1,
                                         uint32_t a2, uint32_t a3,
                                         uint32_t b0, uint32_t b1) {
    asm volatile(
        "mma.sync.aligned.m16n8k16.row.col.f32.bf16.bf16.f32 "
        "{%0,%1,%2,%3}, {%4,%5,%6,%7}, {%8,%9}, {%0,%1,%2,%3};"
        : "+f"(d[0]), "+f"(d[1]), "+f"(d[2]), "+f"(d[3])
        : "r"(a0), "r"(a1), "r"(a2), "r"(a3), "r"(b0), "r"(b1));
}
// x4 ldmatrix, non-trans only. Lane addressing: row=(lane&15), colgroup=(lane>>4).
// m0..m3 == {(r,k),(r+8,k),(r,k+8),(r+8,k+8)} — identical to the validated
// direct-LDS fragment pattern of the R3/R5 gemm.
__device__ __forceinline__ void ldsm_x4(uint32_t* r, uint32_t addr) {
    asm volatile("ldmatrix.sync.aligned.m8n8.x4.shared.b16 {%0,%1,%2,%3}, [%4];"
        : "=r"(r[0]), "=r"(r[1]), "=r"(r[2]), "=r"(r[3]) : "r"(addr));
}
__device__ __forceinline__ uint32_t pack_bf16(float a, float b) {
    __nv_bfloat162 t(__float2bfloat16(a), __float2bfloat16(b));
    return *(uint32_t*)&t;
}

// ---- hi/lo bf16 split -------------------------------------------------------
__global__ __launch_bounds__(256)
void split_bf16(const float4* __restrict__ in, __nv_bfloat16* __restrict__ hi,
                __nv_bfloat16* __restrict__ lo, int n4)
{
    int i = blockIdx.x * 256 + threadIdx.x;
    if (i >= n4) return;
    float4 v = in[i];
    __nv_bfloat16 h0 = __float2bfloat16(v.x), h1 = __float2bfloat16(v.y);
    __nv_bfloat16 h2 = __float2bfloat16(v.z), h3 = __float2bfloat16(v.w);
    __nv_bfloat162* hp = (__nv_bfloat162*)(hi + i * 4);
    __nv_bfloat162* lp = (__nv_bfloat162*)(lo + i * 4);
    hp[0] = __nv_bfloat162(h0, h1);
    hp[1] = __nv_bfloat162(h2, h3);
    lp[0] = __nv_bfloat162(__float2bfloat16(v.x - __bfloat162float(h0)),
                           __float2bfloat16(v.y - __bfloat162float(h1)));
    lp[1] = __nv_bfloat162(__float2bfloat16(v.z - __bfloat162float(h2)),
                           __float2bfloat16(v.w - __bfloat162float(h3)));
}

// ---- bf16x3 mma.sync GEMM with ldmatrix fragment loads ----------------------
#define BM 128
#define BN 128
#define BK 32
#define SROW 40
#define TILE_E (128 * SROW)
#define STAGE_E (4 * TILE_E)
#define SMEM_SZ (2 * STAGE_E * 2)

__global__ __launch_bounds__(256, 1)
void gemm_bf16x3(const __nv_bfloat16* __restrict__ Ahi, const __nv_bfloat16* __restrict__ Alo,
                 const __nv_bfloat16* __restrict__ Bhi, const __nv_bfloat16* __restrict__ Blo,
                 const float* __restrict__ bias, float* __restrict__ C,
                 int M, int N, int K)
{
    extern __shared__ __nv_bfloat16 smem[];
    const int tid  = threadIdx.x;
    const int lane = tid & 31;
    const int wid  = tid >> 5;
    const int wm   = wid >> 2;
    const int wn   = wid & 3;
    const int tr   = lane >> 2;
    const int tc2  = (lane & 3) * 2;
    const int bm   = blockIdx.y * BM;
    const int bn   = blockIdx.x * BN;

    const uint32_t sbase = smem_u32(smem);
    const int lrow = lane & 15;          // ldmatrix row within 16
    const int lcol = (lane >> 4) * 8;    // ldmatrix col group

    float acc[4][4][4];
#pragma unroll
    for (int i = 0; i < 4; ++i)
#pragma unroll
        for (int j = 0; j < 4; ++j)
#pragma unroll
            for (int r = 0; r < 4; ++r) acc[i][j][r] = 0.f;

    const __nv_bfloat16* srcs[4] = { Ahi, Alo, Bhi, Blo };
    const int rowoff[4] = { bm, bm, bn, bn };

    auto load_stage = [&](int s, int k0) {
        const uint32_t st = sbase + (uint32_t)(s * STAGE_E * 2);
#pragma unroll
        for (int t = 0; t < 4; ++t) {
#pragma unroll
            for (int g2 = 0; g2 < 2; ++g2) {
                const int g = tid + g2 * 256;
                const int row = g >> 2, part = g & 3;
                const uint32_t dst = st + (uint32_t)(t * TILE_E + row * SROW + part * 8) * 2;
                const __nv_bfloat16* src = srcs[t] + (size_t)(rowoff[t] + row) * K + k0 + part * 8;
                cp16(dst, src);
            }
        }
    };

    const int KCH = K / BK;
    load_stage(0, 0);
    CP_COMMIT();

    for (int c = 0; c < KCH; ++c) {
        if (c + 1 < KCH) {
            load_stage((c + 1) & 1, (c + 1) * BK);
            CP_COMMIT();
            CP_WAIT(1);
        } else {
            CP_WAIT(0);
        }
        __syncthreads();

        const uint32_t stg = sbase + (uint32_t)((c & 1) * STAGE_E * 2);
        const uint32_t sAh = stg;
        const uint32_t sAl = stg + TILE_E * 2;
        const uint32_t sBh = stg + 2 * TILE_E * 2;
        const uint32_t sBl = stg + 3 * TILE_E * 2;

#pragma unroll
        for (int k0 = 0; k0 < BK; k0 += 16) {
            uint32_t ah[4][4], al[4][4], bh[2][4], bl[2][4];
#pragma unroll
            for (int mi = 0; mi < 4; ++mi) {
                const uint32_t off =
                    (uint32_t)((wm * 64 + mi * 16 + lrow) * SROW + k0 + lcol) * 2;
                ldsm_x4(ah[mi], sAh + off);
                ldsm_x4(al[mi], sAl + off);
            }
#pragma unroll
            for (int p = 0; p < 2; ++p) {
                const uint32_t off =
                    (uint32_t)((wn * 32 + p * 16 + lrow) * SROW + k0 + lcol) * 2;
                ldsm_x4(bh[p], sBh + off);
                ldsm_x4(bl[p], sBl + off);
            }
#pragma unroll
            for (int mi = 0; mi < 4; ++mi)
#pragma unroll
                for (int ni = 0; ni < 4; ++ni) {
                    const int p = ni >> 1, od = ni & 1;
                    const uint32_t b0 = bh[p][0 + od], b1 = bh[p][2 + od];
                    const uint32_t c0 = bl[p][0 + od], c1 = bl[p][2 + od];
                    mma_bf16(acc[mi][ni], ah[mi][0], ah[mi][1], ah[mi][2], ah[mi][3], b0, b1);
                    mma_bf16(acc[mi][ni], al[mi][0], al[mi][1], al[mi][2], al[mi][3], b0, b1);
                    mma_bf16(acc[mi][ni], ah[mi][0], ah[mi][1], ah[mi][2], ah[mi][3], c0, c1);
                }
        }
        __syncthreads();
    }

#pragma unroll
    for (int mi = 0; mi < 4; ++mi) {
        const int r = bm + wm * 64 + mi * 16 + tr;
#pragma unroll
        for (int ni = 0; ni < 4; ++ni) {
            const int cidx = bn + wn * 32 + ni * 8 + tc2;
            const float b0 = bias[cidx], b1 = bias[cidx + 1];
            float2 v0 = make_float2(acc[mi][ni][0] + b0, acc[mi][ni][1] + b1);
            float2 v1 = make_float2(acc[mi][ni][2] + b0, acc[mi][ni][3] + b1);
            *(float2*)(C + (size_t)r * N + cidx)       = v0;
            *(float2*)(C + (size_t)(r + 8) * N + cidx) = v1;
        }
    }
}

// ---- tensor-core sliding-window attention (ldmatrix fragments) --------------
#define SROW2 72
#define QTILE_E (64 * SROW2)
#define SWA_SMEM (6 * QTILE_E * 2)

__device__ __forceinline__ void store_hilo(__nv_bfloat16* H, __nv_bfloat16* L,
                                           int off, float4 v) {
    __nv_bfloat16 h0 = __float2bfloat16(v.x), h1 = __float2bfloat16(v.y);
    __nv_bfloat16 h2 = __float2bfloat16(v.z), h3 = __float2bfloat16(v.w);
    *(__nv_bfloat162*)(H + off)     = __nv_bfloat162(h0, h1);
    *(__nv_bfloat162*)(H + off + 2) = __nv_bfloat162(h2, h3);
    *(__nv_bfloat162*)(L + off)     = __nv_bfloat162(
        __float2bfloat16(v.x - __bfloat162float(h0)),
        __float2bfloat16(v.y - __bfloat162float(h1)));
    *(__nv_bfloat162*)(L + off + 2) = __nv_bfloat162(
        __float2bfloat16(v.z - __bfloat162float(h2)),
        __float2bfloat16(v.w - __bfloat162float(h3)));
}

__global__ __launch_bounds__(128, 2)
void swa_tensor(const float* __restrict__ qkv,
                __nv_bfloat16* __restrict__ ohi, __nv_bfloat16* __restrict__ olo)
{
    extern __shared__ __nv_bfloat16 sm[];
    __nv_bfloat16* Qh  = sm;
    __nv_bfloat16* Ql  = sm + 1 * QTILE_E;
    __nv_bfloat16* Kh  = sm + 2 * QTILE_E;
    __nv_bfloat16* Kl  = sm + 3 * QTILE_E;
    __nv_bfloat16* Vth = sm + 4 * QTILE_E;   // [e][key] (pre-transposed)
    __nv_bfloat16* Vtl = sm + 5 * QTILE_E;

    const int tid = threadIdx.x, lane = tid & 31, w = tid >> 5;
    const int bh = blockIdx.y, b = bh >> 4, h = bh & 15;
    const int q0 = blockIdx.x * 64;
    const int tr = lane >> 2, tc2 = (lane & 3) * 2;
    const int lrow = lane & 15, lcol = (lane >> 4) * 8;

    const size_t rowbase = (size_t)(b * SEQ) * QKV_LD + (size_t)h * HDIM;

    // ---- Q tile -> smem hi/lo ----
#pragma unroll
    for (int it = 0; it < 8; ++it) {
        const int idx = it * 128 + tid;
        const int row = idx >> 4, c4 = (idx & 15) * 4;
        float4 v = *(const float4*)(qkv + rowbase + (size_t)(q0 + row) * QKV_LD + c4);
        store_hilo(Qh, Ql, row * SROW2 + c4, v);
    }
    __syncthreads();

    const uint32_t sQh = smem_u32(Qh), sQl = smem_u32(Ql);
    const uint32_t sKh = smem_u32(Kh), sKl = smem_u32(Kl);
    const uint32_t sVh = smem_u32(Vth), sVl = smem_u32(Vtl);

    // ---- Q A-fragments via ldmatrix ----
    uint32_t qh[4][4], ql[4][4];
#pragma unroll
    for (int ks = 0; ks < 4; ++ks) {
        const uint32_t off = (uint32_t)((w * 16 + lrow) * SROW2 + ks * 16 + lcol) * 2;
        ldsm_x4(qh[ks], sQh + off);
        ldsm_x4(ql[ks], sQl + off);
    }

    float o[8][4];
#pragma unroll
    for (int ni = 0; ni < 8; ++ni)
#pragma unroll
        for (int j = 0; j < 4; ++j) o[ni][j] = 0.f;
    float m0 = -1e30f, m1 = -1e30f, l0 = 0.f, l1 = 0.f;
    const int i0 = q0 + w * 16 + tr;
    const int i1 = i0 + 8;

    const int kt0 = max(0, (int)blockIdx.x - 4);
    const int kt1 = blockIdx.x;

    for (int kt = kt0; kt <= kt1; ++kt) {
        const int j0 = kt * 64;
        __syncthreads();
#pragma unroll
        for (int it = 0; it < 8; ++it) {
            const int idx = it * 128 + tid;
            const int row = idx >> 4, c4 = (idx & 15) * 4;   // row = key, c4 = e
            const size_t rb = rowbase + (size_t)(j0 + row) * QKV_LD;
            float4 kv = *(const float4*)(qkv + rb + D_MODEL + c4);
            float4 vv = *(const float4*)(qkv + rb + 2 * D_MODEL + c4);
            store_hilo(Kh, Kl, row * SROW2 + c4, kv);
            const float vf[4] = { vv.x, vv.y, vv.z, vv.w };
#pragma unroll
            for (int j = 0; j < 4; ++j) {
                __nv_bfloat16 hv = __float2bfloat16(vf[j]);
                Vth[(c4 + j) * SROW2 + row] = hv;
                Vtl[(c4 + j) * SROW2 + row] =
                    __float2bfloat16(vf[j] - __bfloat162float(hv));
            }
        }
        __syncthreads();

        // ---- S = Q K^T (bf16x3), K B-fragments via ldmatrix ----
        float s[8][4];
#pragma unroll
        for (int ni = 0; ni < 8; ++ni)
#pragma unroll
            for (int j = 0; j < 4; ++j) s[ni][j] = 0.f;

#pragma unroll
        for (int p = 0; p < 4; ++p) {             // key 16-pair (ni=2p,2p+1)
#pragma unroll
            for (int ks = 0; ks < 4; ++ks) {      // e 16-block
                uint32_t kb[4], kl[4];
                const uint32_t off =
                    (uint32_t)((p * 16 + lrow) * SROW2 + ks * 16 + lcol) * 2;
                ldsm_x4(kb, sKh + off);
                ldsm_x4(kl, sKl + off);
                mma_bf16(s[2*p],   qh[ks][0], qh[ks][1], qh[ks][2], qh[ks][3], kb[0], kb[2]);
                mma_bf16(s[2*p],   ql[ks][0], ql[ks][1], ql[ks][2], ql[ks][3], kb[0], kb[2]);
                mma_bf16(s[2*p],   qh[ks][0], qh[ks][1], qh[ks][2], qh[ks][3], kl[0], kl[2]);
                mma_bf16(s[2*p+1], qh[ks][0], qh[ks][1], qh[ks][2], qh[ks][3], kb[1], kb[3]);
                mma_bf16(s[2*p+1], ql[ks][0], ql[ks][1], ql[ks][2], ql[ks][3], kb[1], kb[3]);
                mma_bf16(s[2*p+1], qh[ks][0], qh[ks][1], qh[ks][2], qh[ks][3], kl[1], kl[3]);
            }
        }

        // ---- mask + online softmax ----
        float tmax0 = -1e30f, tmax1 = -1e30f;
#pragma unroll
        for (int ni = 0; ni < 8; ++ni) {
            const int ja = j0 + ni * 8 + tc2, jb = ja + 1;
            s[ni][0] = (ja <= i0 && (i0 - ja) < WINDOW) ? s[ni][0] * 0.125f : -1e30f;
            s[ni][1] = (jb <= i0 && (i0 - jb) < WINDOW) ? s[ni][1] * 0.125f : -1e30f;
            s[ni][2] = (ja <= i1 && (i1 - ja) < WINDOW) ? s[ni][2] * 0.125f : -1e30f;
            s[ni][3] = (jb <= i1 && (i1 - jb) < WINDOW) ? s[ni][3] * 0.125f : -1e30f;
            tmax0 = fmaxf(tmax0, fmaxf(s[ni][0], s[ni][1]));
            tmax1 = fmaxf(tmax1, fmaxf(s[ni][2], s[ni][3]));
        }
        tmax0 = fmaxf(tmax0, __shfl_xor_sync(0xffffffff, tmax0, 1));
        tmax0 = fmaxf(tmax0, __shfl_xor_sync(0xffffffff, tmax0, 2));
        tmax1 = fmaxf(tmax1, __shfl_xor_sync(0xffffffff, tmax1, 1));
        tmax1 = fmaxf(tmax1, __shfl_xor_sync(0xffffffff, tmax1, 2));

        const float mn0 = fmaxf(m0, tmax0), mn1 = fmaxf(m1, tmax1);
        const float sc0 = __expf(m0 - mn0), sc1 = __expf(m1 - mn1);
        m0 = mn0; m1 = mn1;

        float rs0 = 0.f, rs1 = 0.f;
        uint32_t ph[8][2], pl[8][2];
#pragma unroll
        for (int ni = 0; ni < 8; ++ni) {
            float p0 = __expf(s[ni][0] - mn0);
            float p1 = __expf(s[ni][1] - mn0);
            float p2 = __expf(s[ni][2] - mn1);
            float p3 = __expf(s[ni][3] - mn1);
            rs0 += p0 + p1; rs1 += p2 + p3;
            __nv_bfloat16 b0 = __float2bfloat16(p0), b1 = __float2bfloat16(p1);
            __nv_bfloat16 b2 = __float2bfloat16(p2), b3 = __float2bfloat16(p3);
            __nv_bfloat162 t01(b0, b1), t23(b2, b3);
            ph[ni][0] = *(uint32_t*)&t01;
            ph[ni][1] = *(uint32_t*)&t23;
            pl[ni][0] = pack_bf16(p0 - __bfloat162float(b0), p1 - __bfloat162float(b1));
            pl[ni][1] = pack_bf16(p2 - __bfloat162float(b2), p3 - __bfloat162float(b3));
        }
        rs0 += __shfl_xor_sync(0xffffffff, rs0, 1);
        rs0 += __shfl_xor_sync(0xffffffff, rs0, 2);
        rs1 += __shfl_xor_sync(0xffffffff, rs1, 1);
        rs1 += __shfl_xor_sync(0xffffffff, rs1, 2);
        l0 = l0 * sc0 + rs0;
        l1 = l1 * sc1 + rs1;

#pragma unroll
        for (int ni = 0; ni < 8; ++ni) {
            o[ni][0] *= sc0; o[ni][1] *= sc0;
            o[ni][2] *= sc1; o[ni][3] *= sc1;
        }

        // ---- O += P V (bf16x3); V B-fragments via ldmatrix on transposed V ----
#pragma unroll
        for (int p = 0; p < 4; ++p) {             // e 16-pair (out cols ni=2p,2p+1)
#pragma unroll
            for (int ks = 0; ks < 4; ++ks) {      // key 16-block
                uint32_t vb[4], vl[4];
                const uint32_t off =
                    (uint32_t)((p * 16 + lrow) * SROW2 + ks * 16 + lcol) * 2;
                ldsm_x4(vb, sVh + off);
                ldsm_x4(vl, sVl + off);
                mma_bf16(o[2*p],   ph[2*ks][0], ph[2*ks][1], ph[2*ks+1][0], ph[2*ks+1][1], vb[0], vb[2]);
                mma_bf16(o[2*p],   pl[2*ks][0], pl[2*ks][1], pl[2*ks+1][0], pl[2*ks+1][1], vb[0], vb[2]);
                mma_bf16(o[2*p],   ph[2*ks][0], ph[2*ks][1], ph[2*ks+1][0], ph[2*ks+1][1], vl[0], vl[2]);
                mma_bf16(o[2*p+1], ph[2*ks][0], ph[2*ks][1], ph[2*ks+1][0], ph[2*ks+1][1], vb[1], vb[3]);
                mma_bf16(o[2*p+1], pl[2*ks][0], pl[2*ks][1], pl[2*ks+1][0], pl[2*ks+1][1], vb[1], vb[3]);
                mma_bf16(o[2*p+1], ph[2*ks][0], ph[2*ks][1], ph[2*ks+1][0], ph[2*ks+1][1], vl[1], vl[3]);
            }
        }
    }

    // ---- epilogue ----
    const float inv0 = 1.f / l0, inv1 = 1.f / l1;
    const size_t t0 = (size_t)(b * SEQ + i0) * D_MODEL + (size_t)h * HDIM;
    const size_t t1 = (size_t)(b * SEQ + i1) * D_MODEL + (size_t)h * HDIM;
#pragma unroll
    for (int ni = 0; ni < 8; ++ni) {
        const int c = ni * 8 + tc2;
        float f0 = o[ni][0] * inv0, f1 = o[ni][1] * inv0;
        float f2 = o[ni][2] * inv1, f3 = o[ni][3] * inv1;
        __nv_bfloat16 h0 = __float2bfloat16(f0), h1 = __float2bfloat16(f1);
        __nv_bfloat16 h2 = __float2bfloat16(f2), h3 = __float2bfloat16(f3);
        __nv_bfloat162 u01(h0, h1), u23(h2, h3);
        *(uint32_t*)(ohi + t0 + c) = *(uint32_t*)&u01;
        *(uint32_t*)(ohi + t1 + c) = *(uint32_t*)&u23;
        *(uint32_t*)(olo + t0 + c) = pack_bf16(f0 - __bfloat162float(h0),
                                               f1 - __bfloat162float(h1));
        *(uint32_t*)(olo + t1 + c) = pack_bf16(f2 - __bfloat162float(h2),
                                               f3 - __bfloat162float(h3));
    }
}

// ---------------------------------------------------------------------------
extern "C" void kernel_launch(void* const* d_in, const int* in_sizes, int n_in,
                              void* d_out, int out_size)
{
    const float* x      = (const float*)d_in[0];
    const float* w_qkv  = (const float*)d_in[1];
    const float* b_qkv  = (const float*)d_in[2];
    const float* w_proj = (const float*)d_in[3];
    const float* b_proj = (const float*)d_in[4];
    float* out = (float*)d_out;

    float* qkv_p;
    __nv_bfloat16 *xhi, *xlo, *wqh, *wql, *wph, *wpl, *ahi, *alo;
    cudaGetSymbolAddress((void**)&qkv_p, g_qkv);
    cudaGetSymbolAddress((void**)&xhi, g_xhi);
    cudaGetSymbolAddress((void**)&xlo, g_xlo);
    cudaGetSymbolAddress((void**)&wqh, g_wqh);
    cudaGetSymbolAddress((void**)&wql, g_wql);
    cudaGetSymbolAddress((void**)&wph, g_wph);
    cudaGetSymbolAddress((void**)&wpl, g_wpl);
    cudaGetSymbolAddress((void**)&ahi, g_ahi);
    cudaGetSymbolAddress((void**)&alo, g_alo);

    cudaFuncSetAttribute(gemm_bf16x3,
                         cudaFuncAttributeMaxDynamicSharedMemorySize, SMEM_SZ);
    cudaFuncSetAttribute(swa_tensor,
                         cudaFuncAttributeMaxDynamicSharedMemorySize, SWA_SMEM);

    {
        int n4x = MTOT * D_MODEL / 4;
        int n4q = QKV_LD * D_MODEL / 4;
        int n4p = D_MODEL * D_MODEL / 4;
        split_bf16<<<n4x / 256, 256>>>((const float4*)x, xhi, xlo, n4x);
        split_bf16<<<n4q / 256, 256>>>((const float4*)w_qkv, wqh, wql, n4q);
        split_bf16<<<n4p / 256, 256>>>((const float4*)w_proj, wph, wpl, n4p);
    }

    // 1) QKV projection (bf16x3 tensor-core)
    gemm_bf16x3<<<dim3(QKV_LD / BN, MTOT / BM), 256, SMEM_SZ>>>(
        xhi, xlo, wqh, wql, b_qkv, qkv_p, MTOT, QKV_LD, D_MODEL);

    // 2) tensor-core sliding-window attention -> bf16 hi/lo
    swa_tensor<<<dim3(SEQ / 64, BATCH * NHEADS), 128, SWA_SMEM>>>(qkv_p, ahi, alo);

    // 3) output projection (bf16x3 tensor-core)
    gemm_bf16x3<<<dim3(D_MODEL / BN, MTOT / BM), 256, SMEM_SZ>>>(
        ahi, alo, wph, wpl, b_proj, out, MTOT, D_MODEL, D_MODEL);
}

// round 7
// speedup vs baseline: 1.1812x; 1.1812x over previous
#include <cuda_runtime.h>
#include <cuda_bf16.h>
#include <cstdint>

#define D_MODEL 1024
#define NHEADS  16
#define HDIM    64
#define WINDOW  256
#define BATCH   2
#define SEQ     2048
#define MTOT    (BATCH * SEQ)          /* 4096 */
#define QKV_LD  (3 * D_MODEL)          /* 3072 */

// ---- scratch (no cudaMalloc allowed) --------------------------------------
__device__ float        g_qkv[(size_t)MTOT * QKV_LD];
__device__ __nv_bfloat16 g_xhi[(size_t)MTOT * D_MODEL];
__device__ __nv_bfloat16 g_xlo[(size_t)MTOT * D_MODEL];
__device__ __nv_bfloat16 g_wqh[(size_t)QKV_LD * D_MODEL];
__device__ __nv_bfloat16 g_wql[(size_t)QKV_LD * D_MODEL];
__device__ __nv_bfloat16 g_wph[(size_t)D_MODEL * D_MODEL];
__device__ __nv_bfloat16 g_wpl[(size_t)D_MODEL * D_MODEL];
__device__ __nv_bfloat16 g_ahi[(size_t)MTOT * D_MODEL];
__device__ __nv_bfloat16 g_alo[(size_t)MTOT * D_MODEL];

// ---- PTX helpers (compute_103 baseline: mma.sync + cp.async) ---------------
__device__ __forceinline__ uint32_t smem_u32(const void* p) {
    uint32_t a;
    asm("{ .reg .u64 t; cvta.to.shared.u64 t, %1; cvt.u32.u64 %0, t; }" : "=r"(a) : "l"(p));
    return a;
}
__device__ __forceinline__ void cp16(uint32_t dst, const void* src) {
    asm volatile("cp.async.cg.shared.global [%0], [%1], 16;" :: "r"(dst), "l"(src));
}
#define CP_COMMIT()  asm volatile("cp.async.commit_group;" ::: "memory")
#define CP_WAIT(n)   asm volatile("cp.async.wait_group %0;" :: "n"(n) : "memory")

__device__ __forceinline__ void mma_bf16(float* d, uint32_t a0, uint32_t a1,
                                         uint32_t a2, uint32_t a3,
                                         uint32_t b0, uint32_t b1) {
    asm volatile(
        "mma.sync.aligned.m16n8k16.row.col.f32.bf16.bf16.f32 "
        "{%0,%1,%2,%3}, {%4,%5,%6,%7}, {%8,%9}, {%0,%1,%2,%3};"
        : "+f"(d[0]), "+f"(d[1]), "+f"(d[2]), "+f"(d[3])
        : "r"(a0), "r"(a1), "r"(a2), "r"(a3), "r"(b0), "r"(b1));
}
__device__ __forceinline__ uint32_t pack_bf16(float a, float b) {
    __nv_bfloat162 t(__float2bfloat16(a), __float2bfloat16(b));
    return *(uint32_t*)&t;
}

// ---- hi/lo bf16 split -------------------------------------------------------
__global__ __launch_bounds__(256)
void split_bf16(const float4* __restrict__ in, __nv_bfloat16* __restrict__ hi,
                __nv_bfloat16* __restrict__ lo, int n4)
{
    int i = blockIdx.x * 256 + threadIdx.x;
    if (i >= n4) return;
    float4 v = in[i];
    __nv_bfloat16 h0 = __float2bfloat16(v.x), h1 = __float2bfloat16(v.y);
    __nv_bfloat16 h2 = __float2bfloat16(v.z), h3 = __float2bfloat16(v.w);
    __nv_bfloat162* hp = (__nv_bfloat162*)(hi + i * 4);
    __nv_bfloat162* lp = (__nv_bfloat162*)(lo + i * 4);
    hp[0] = __nv_bfloat162(h0, h1);
    hp[1] = __nv_bfloat162(h2, h3);
    lp[0] = __nv_bfloat162(__float2bfloat16(v.x - __bfloat162float(h0)),
                           __float2bfloat16(v.y - __bfloat162float(h1)));
    lp[1] = __nv_bfloat162(__float2bfloat16(v.z - __bfloat162float(h2)),
                           __float2bfloat16(v.w - __bfloat162float(h3)));
}

// ---- bf16x3 mma.sync GEMM (R5 direct-LDS body; now 2 CTAs/SM) ---------------
#define BM 128
#define BN 128
#define BK 32
#define SROW 40
#define TILE_E (128 * SROW)
#define STAGE_E (4 * TILE_E)
#define SMEM_SZ (2 * STAGE_E * 2)

__global__ __launch_bounds__(256, 2)
void gemm_bf16x3(const __nv_bfloat16* __restrict__ Ahi, const __nv_bfloat16* __restrict__ Alo,
                 const __nv_bfloat16* __restrict__ Bhi, const __nv_bfloat16* __restrict__ Blo,
                 const float* __restrict__ bias, float* __restrict__ C,
                 int M, int N, int K)
{
    extern __shared__ __nv_bfloat16 smem[];
    const int tid  = threadIdx.x;
    const int lane = tid & 31;
    const int wid  = tid >> 5;
    const int wm   = wid >> 2;
    const int wn   = wid & 3;
    const int tr   = lane >> 2;
    const int tc2  = (lane & 3) * 2;
    const int bm   = blockIdx.y * BM;
    const int bn   = blockIdx.x * BN;

    const uint32_t sbase = smem_u32(smem);

    float acc[4][4][4];
#pragma unroll
    for (int i = 0; i < 4; ++i)
#pragma unroll
        for (int j = 0; j < 4; ++j)
#pragma unroll
            for (int r = 0; r < 4; ++r) acc[i][j][r] = 0.f;

    const __nv_bfloat16* srcs[4] = { Ahi, Alo, Bhi, Blo };
    const int rowoff[4] = { bm, bm, bn, bn };

    auto load_stage = [&](int s, int k0) {
        const uint32_t st = sbase + (uint32_t)(s * STAGE_E * 2);
#pragma unroll
        for (int t = 0; t < 4; ++t) {
#pragma unroll
            for (int g2 = 0; g2 < 2; ++g2) {
                const int g = tid + g2 * 256;
                const int row = g >> 2, part = g & 3;
                const uint32_t dst = st + (uint32_t)(t * TILE_E + row * SROW + part * 8) * 2;
                const __nv_bfloat16* src = srcs[t] + (size_t)(rowoff[t] + row) * K + k0 + part * 8;
                cp16(dst, src);
            }
        }
    };

    const int KCH = K / BK;
    load_stage(0, 0);
    CP_COMMIT();

    for (int c = 0; c < KCH; ++c) {
        if (c + 1 < KCH) {
            load_stage((c + 1) & 1, (c + 1) * BK);
            CP_COMMIT();
            CP_WAIT(1);
        } else {
            CP_WAIT(0);
        }
        __syncthreads();

        const __nv_bfloat16* stg = smem + (c & 1) * STAGE_E;
        const __nv_bfloat16* Ah = stg;
        const __nv_bfloat16* Al = stg + TILE_E;
        const __nv_bfloat16* Bh = stg + 2 * TILE_E;
        const __nv_bfloat16* Bl = stg + 3 * TILE_E;

#pragma unroll
        for (int k0 = 0; k0 < BK; k0 += 16) {
            uint32_t ah[4][4], al[4][4], bh[4][2], bl[4][2];
#pragma unroll
            for (int mi = 0; mi < 4; ++mi) {
                const int base = (wm * 64 + mi * 16 + tr) * SROW + k0 + tc2;
                ah[mi][0] = *(const uint32_t*)(Ah + base);
                ah[mi][1] = *(const uint32_t*)(Ah + base + 8 * SROW);
                ah[mi][2] = *(const uint32_t*)(Ah + base + 8);
                ah[mi][3] = *(const uint32_t*)(Ah + base + 8 * SROW + 8);
                al[mi][0] = *(const uint32_t*)(Al + base);
                al[mi][1] = *(const uint32_t*)(Al + base + 8 * SROW);
                al[mi][2] = *(const uint32_t*)(Al + base + 8);
                al[mi][3] = *(const uint32_t*)(Al + base + 8 * SROW + 8);
            }
#pragma unroll
            for (int ni = 0; ni < 4; ++ni) {
                const int base = (wn * 32 + ni * 8 + tr) * SROW + k0 + tc2;
                bh[ni][0] = *(const uint32_t*)(Bh + base);
                bh[ni][1] = *(const uint32_t*)(Bh + base + 8);
                bl[ni][0] = *(const uint32_t*)(Bl + base);
                bl[ni][1] = *(const uint32_t*)(Bl + base + 8);
            }
#pragma unroll
            for (int mi = 0; mi < 4; ++mi)
#pragma unroll
                for (int ni = 0; ni < 4; ++ni) {
                    mma_bf16(acc[mi][ni], ah[mi][0], ah[mi][1], ah[mi][2], ah[mi][3],
                             bh[ni][0], bh[ni][1]);
                    mma_bf16(acc[mi][ni], al[mi][0], al[mi][1], al[mi][2], al[mi][3],
                             bh[ni][0], bh[ni][1]);
                    mma_bf16(acc[mi][ni], ah[mi][0], ah[mi][1], ah[mi][2], ah[mi][3],
                             bl[ni][0], bl[ni][1]);
                }
        }
        __syncthreads();
    }

#pragma unroll
    for (int mi = 0; mi < 4; ++mi) {
        const int r = bm + wm * 64 + mi * 16 + tr;
#pragma unroll
        for (int ni = 0; ni < 4; ++ni) {
            const int cidx = bn + wn * 32 + ni * 8 + tc2;
            const float b0 = bias[cidx], b1 = bias[cidx + 1];
            float2 v0 = make_float2(acc[mi][ni][0] + b0, acc[mi][ni][1] + b1);
            float2 v1 = make_float2(acc[mi][ni][2] + b0, acc[mi][ni][3] + b1);
            *(float2*)(C + (size_t)r * N + cidx)       = v0;
            *(float2*)(C + (size_t)(r + 8) * N + cidx) = v1;
        }
    }
}

// ---- tensor-core sliding-window attention (R5 direct-LDS, validated) --------
#define SROW2 72
#define QTILE_E (64 * SROW2)
#define SWA_SMEM (6 * QTILE_E * 2)

__device__ __forceinline__ void store_hilo(__nv_bfloat16* H, __nv_bfloat16* L,
                                           int off, float4 v) {
    __nv_bfloat16 h0 = __float2bfloat16(v.x), h1 = __float2bfloat16(v.y);
    __nv_bfloat16 h2 = __float2bfloat16(v.z), h3 = __float2bfloat16(v.w);
    *(__nv_bfloat162*)(H + off)     = __nv_bfloat162(h0, h1);
    *(__nv_bfloat162*)(H + off + 2) = __nv_bfloat162(h2, h3);
    *(__nv_bfloat162*)(L + off)     = __nv_bfloat162(
        __float2bfloat16(v.x - __bfloat162float(h0)),
        __float2bfloat16(v.y - __bfloat162float(h1)));
    *(__nv_bfloat162*)(L + off + 2) = __nv_bfloat162(
        __float2bfloat16(v.z - __bfloat162float(h2)),
        __float2bfloat16(v.w - __bfloat162float(h3)));
}

__global__ __launch_bounds__(128, 2)
void swa_tensor(const float* __restrict__ qkv,
                __nv_bfloat16* __restrict__ ohi, __nv_bfloat16* __restrict__ olo)
{
    extern __shared__ __nv_bfloat16 sm[];
    __nv_bfloat16* Qh  = sm;
    __nv_bfloat16* Ql  = sm + 1 * QTILE_E;
    __nv_bfloat16* Kh  = sm + 2 * QTILE_E;
    __nv_bfloat16* Kl  = sm + 3 * QTILE_E;
    __nv_bfloat16* Vth = sm + 4 * QTILE_E;   // [e][key]
    __nv_bfloat16* Vtl = sm + 5 * QTILE_E;

    const int tid = threadIdx.x, lane = tid & 31, w = tid >> 5;
    const int bh = blockIdx.y, b = bh >> 4, h = bh & 15;
    const int q0 = blockIdx.x * 64;
    const int tr = lane >> 2, tc2 = (lane & 3) * 2;

    const size_t rowbase = (size_t)(b * SEQ) * QKV_LD + (size_t)h * HDIM;

    // ---- Q tile -> smem hi/lo ----
#pragma unroll
    for (int it = 0; it < 8; ++it) {
        const int idx = it * 128 + tid;
        const int row = idx >> 4, c4 = (idx & 15) * 4;
        float4 v = *(const float4*)(qkv + rowbase + (size_t)(q0 + row) * QKV_LD + c4);
        store_hilo(Qh, Ql, row * SROW2 + c4, v);
    }
    __syncthreads();

    // ---- Q A-fragments via direct LDS ----
    uint32_t qh[4][4], ql[4][4];
#pragma unroll
    for (int ks = 0; ks < 4; ++ks) {
        const int base = (w * 16 + tr) * SROW2 + ks * 16 + tc2;
        qh[ks][0] = *(const uint32_t*)(Qh + base);
        qh[ks][1] = *(const uint32_t*)(Qh + base + 8 * SROW2);
        qh[ks][2] = *(const uint32_t*)(Qh + base + 8);
        qh[ks][3] = *(const uint32_t*)(Qh + base + 8 * SROW2 + 8);
        ql[ks][0] = *(const uint32_t*)(Ql + base);
        ql[ks][1] = *(const uint32_t*)(Ql + base + 8 * SROW2);
        ql[ks][2] = *(const uint32_t*)(Ql + base + 8);
        ql[ks][3] = *(const uint32_t*)(Ql + base + 8 * SROW2 + 8);
    }

    float o[8][4];
#pragma unroll
    for (int ni = 0; ni < 8; ++ni)
#pragma unroll
        for (int j = 0; j < 4; ++j) o[ni][j] = 0.f;
    float m0 = -1e30f, m1 = -1e30f, l0 = 0.f, l1 = 0.f;
    const int i0 = q0 + w * 16 + tr;
    const int i1 = i0 + 8;

    const int kt0 = max(0, (int)blockIdx.x - 4);
    const int kt1 = blockIdx.x;

    for (int kt = kt0; kt <= kt1; ++kt) {
        const int j0 = kt * 64;
        __syncthreads();
#pragma unroll
        for (int it = 0; it < 8; ++it) {
            const int idx = it * 128 + tid;
            const int row = idx >> 4, c4 = (idx & 15) * 4;
            const size_t rb = rowbase + (size_t)(j0 + row) * QKV_LD;
            float4 kv = *(const float4*)(qkv + rb + D_MODEL + c4);
            float4 vv = *(const float4*)(qkv + rb + 2 * D_MODEL + c4);
            store_hilo(Kh, Kl, row * SROW2 + c4, kv);
            const float vf[4] = { vv.x, vv.y, vv.z, vv.w };
#pragma unroll
            for (int j = 0; j < 4; ++j) {
                __nv_bfloat16 hv = __float2bfloat16(vf[j]);
                Vth[(c4 + j) * SROW2 + row] = hv;
                Vtl[(c4 + j) * SROW2 + row] =
                    __float2bfloat16(vf[j] - __bfloat162float(hv));
            }
        }
        __syncthreads();

        // ---- S = Q K^T (bf16x3) ----
        float s[8][4];
#pragma unroll
        for (int ni = 0; ni < 8; ++ni)
#pragma unroll
            for (int j = 0; j < 4; ++j) s[ni][j] = 0.f;

#pragma unroll
        for (int ni = 0; ni < 8; ++ni) {
#pragma unroll
            for (int ks = 0; ks < 4; ++ks) {
                const int base = (ni * 8 + tr) * SROW2 + ks * 16 + tc2;
                const uint32_t kb0 = *(const uint32_t*)(Kh + base);
                const uint32_t kb1 = *(const uint32_t*)(Kh + base + 8);
                const uint32_t kl0 = *(const uint32_t*)(Kl + base);
                const uint32_t kl1 = *(const uint32_t*)(Kl + base + 8);
                mma_bf16(s[ni], qh[ks][0], qh[ks][1], qh[ks][2], qh[ks][3], kb0, kb1);
                mma_bf16(s[ni], ql[ks][0], ql[ks][1], ql[ks][2], ql[ks][3], kb0, kb1);
                mma_bf16(s[ni], qh[ks][0], qh[ks][1], qh[ks][2], qh[ks][3], kl0, kl1);
            }
        }

        // ---- mask + online softmax ----
        float tmax0 = -1e30f, tmax1 = -1e30f;
#pragma unroll
        for (int ni = 0; ni < 8; ++ni) {
            const int ja = j0 + ni * 8 + tc2, jb = ja + 1;
            s[ni][0] = (ja <= i0 && (i0 - ja) < WINDOW) ? s[ni][0] * 0.125f : -1e30f;
            s[ni][1] = (jb <= i0 && (i0 - jb) < WINDOW) ? s[ni][1] * 0.125f : -1e30f;
            s[ni][2] = (ja <= i1 && (i1 - ja) < WINDOW) ? s[ni][2] * 0.125f : -1e30f;
            s[ni][3] = (jb <= i1 && (i1 - jb) < WINDOW) ? s[ni][3] * 0.125f : -1e30f;
            tmax0 = fmaxf(tmax0, fmaxf(s[ni][0], s[ni][1]));
            tmax1 = fmaxf(tmax1, fmaxf(s[ni][2], s[ni][3]));
        }
        tmax0 = fmaxf(tmax0, __shfl_xor_sync(0xffffffff, tmax0, 1));
        tmax0 = fmaxf(tmax0, __shfl_xor_sync(0xffffffff, tmax0, 2));
        tmax1 = fmaxf(tmax1, __shfl_xor_sync(0xffffffff, tmax1, 1));
        tmax1 = fmaxf(tmax1, __shfl_xor_sync(0xffffffff, tmax1, 2));

        const float mn0 = fmaxf(m0, tmax0), mn1 = fmaxf(m1, tmax1);
        const float sc0 = __expf(m0 - mn0), sc1 = __expf(m1 - mn1);
        m0 = mn0; m1 = mn1;

        float rs0 = 0.f, rs1 = 0.f;
        uint32_t ph[8][2], pl[8][2];
#pragma unroll
        for (int ni = 0; ni < 8; ++ni) {
            float p0 = __expf(s[ni][0] - mn0);
            float p1 = __expf(s[ni][1] - mn0);
            float p2 = __expf(s[ni][2] - mn1);
            float p3 = __expf(s[ni][3] - mn1);
            rs0 += p0 + p1; rs1 += p2 + p3;
            __nv_bfloat16 b0 = __float2bfloat16(p0), b1 = __float2bfloat16(p1);
            __nv_bfloat16 b2 = __float2bfloat16(p2), b3 = __float2bfloat16(p3);
            __nv_bfloat162 t01(b0, b1), t23(b2, b3);
            ph[ni][0] = *(uint32_t*)&t01;
            ph[ni][1] = *(uint32_t*)&t23;
            pl[ni][0] = pack_bf16(p0 - __bfloat162float(b0), p1 - __bfloat162float(b1));
            pl[ni][1] = pack_bf16(p2 - __bfloat162float(b2), p3 - __bfloat162float(b3));
        }
        rs0 += __shfl_xor_sync(0xffffffff, rs0, 1);
        rs0 += __shfl_xor_sync(0xffffffff, rs0, 2);
        rs1 += __shfl_xor_sync(0xffffffff, rs1, 1);
        rs1 += __shfl_xor_sync(0xffffffff, rs1, 2);
        l0 = l0 * sc0 + rs0;
        l1 = l1 * sc1 + rs1;

#pragma unroll
        for (int ni = 0; ni < 8; ++ni) {
            o[ni][0] *= sc0; o[ni][1] *= sc0;
            o[ni][2] *= sc1; o[ni][3] *= sc1;
        }

        // ---- O += P V (bf16x3) ----
#pragma unroll
        for (int ni = 0; ni < 8; ++ni) {
#pragma unroll
            for (int ks = 0; ks < 4; ++ks) {
                const int base = (ni * 8 + tr) * SROW2 + ks * 16 + tc2;
                const uint32_t vb0 = *(const uint32_t*)(Vth + base);
                const uint32_t vb1 = *(const uint32_t*)(Vth + base + 8);
                const uint32_t vl0 = *(const uint32_t*)(Vtl + base);
                const uint32_t vl1 = *(const uint32_t*)(Vtl + base + 8);
                mma_bf16(o[ni], ph[2*ks][0], ph[2*ks][1], ph[2*ks+1][0], ph[2*ks+1][1], vb0, vb1);
                mma_bf16(o[ni], pl[2*ks][0], pl[2*ks][1], pl[2*ks+1][0], pl[2*ks+1][1], vb0, vb1);
                mma_bf16(o[ni], ph[2*ks][0], ph[2*ks][1], ph[2*ks+1][0], ph[2*ks+1][1], vl0, vl1);
            }
        }
    }

    // ---- epilogue ----
    const float inv0 = 1.f / l0, inv1 = 1.f / l1;
    const size_t t0 = (size_t)(b * SEQ + i0) * D_MODEL + (size_t)h * HDIM;
    const size_t t1 = (size_t)(b * SEQ + i1) * D_MODEL + (size_t)h * HDIM;
#pragma unroll
    for (int ni = 0; ni < 8; ++ni) {
        const int c = ni * 8 + tc2;
        float f0 = o[ni][0] * inv0, f1 = o[ni][1] * inv0;
        float f2 = o[ni][2] * inv1, f3 = o[ni][3] * inv1;
        __nv_bfloat16 h0 = __float2bfloat16(f0), h1 = __float2bfloat16(f1);
        __nv_bfloat16 h2 = __float2bfloat16(f2), h3 = __float2bfloat16(f3);
        __nv_bfloat162 u01(h0, h1), u23(h2, h3);
        *(uint32_t*)(ohi + t0 + c) = *(uint32_t*)&u01;
        *(uint32_t*)(ohi + t1 + c) = *(uint32_t*)&u23;
        *(uint32_t*)(olo + t0 + c) = pack_bf16(f0 - __bfloat162float(h0),
                                               f1 - __bfloat162float(h1));
        *(uint32_t*)(olo + t1 + c) = pack_bf16(f2 - __bfloat162float(h2),
                                               f3 - __bfloat162float(h3));
    }
}

// ---------------------------------------------------------------------------
extern "C" void kernel_launch(void* const* d_in, const int* in_sizes, int n_in,
                              void* d_out, int out_size)
{
    const float* x      = (const float*)d_in[0];
    const float* w_qkv  = (const float*)d_in[1];
    const float* b_qkv  = (const float*)d_in[2];
    const float* w_proj = (const float*)d_in[3];
    const float* b_proj = (const float*)d_in[4];
    float* out = (float*)d_out;

    float* qkv_p;
    __nv_bfloat16 *xhi, *xlo, *wqh, *wql, *wph, *wpl, *ahi, *alo;
    cudaGetSymbolAddress((void**)&qkv_p, g_qkv);
    cudaGetSymbolAddress((void**)&xhi, g_xhi);
    cudaGetSymbolAddress((void**)&xlo, g_xlo);
    cudaGetSymbolAddress((void**)&wqh, g_wqh);
    cudaGetSymbolAddress((void**)&wql, g_wql);
    cudaGetSymbolAddress((void**)&wph, g_wph);
    cudaGetSymbolAddress((void**)&wpl, g_wpl);
    cudaGetSymbolAddress((void**)&ahi, g_ahi);
    cudaGetSymbolAddress((void**)&alo, g_alo);

    cudaFuncSetAttribute(gemm_bf16x3,
                         cudaFuncAttributeMaxDynamicSharedMemorySize, SMEM_SZ);
    cudaFuncSetAttribute(swa_tensor,
                         cudaFuncAttributeMaxDynamicSharedMemorySize, SWA_SMEM);

    {
        int n4x = MTOT * D_MODEL / 4;
        int n4q = QKV_LD * D_MODEL / 4;
        int n4p = D_MODEL * D_MODEL / 4;
        split_bf16<<<n4x / 256, 256>>>((const float4*)x, xhi, xlo, n4x);
        split_bf16<<<n4q / 256, 256>>>((const float4*)w_qkv, wqh, wql, n4q);
        split_bf16<<<n4p / 256, 256>>>((const float4*)w_proj, wph, wpl, n4p);
    }

    // 1) QKV projection (bf16x3 tensor-core)
    gemm_bf16x3<<<dim3(QKV_LD / BN, MTOT / BM), 256, SMEM_SZ>>>(
        xhi, xlo, wqh, wql, b_qkv, qkv_p, MTOT, QKV_LD, D_MODEL);

    // 2) tensor-core sliding-window attention -> bf16 hi/lo
    swa_tensor<<<dim3(SEQ / 64, BATCH * NHEADS), 128, SWA_SMEM>>>(qkv_p, ahi, alo);

    // 3) output projection (bf16x3 tensor-core)
    gemm_bf16x3<<<dim3(D_MODEL / BN, MTOT / BM), 256, SMEM_SZ>>>(
        ahi, alo, wph, wpl, b_proj, out, MTOT, D_MODEL, D_MODEL);
}